// round 7
// baseline (speedup 1.0000x reference)
#include <cuda_runtime.h>
#include <cstdint>

#define BB 4
#define NN 50000
#define EE 800000
#define FF 128
#define NBLK 49           // ceil(NN/1024)
#define NTILES 12500      // 16-row warp tiles (200000/16)
#define HB ((size_t)NN * FF)

// ---------------- scratch (__device__ globals: allocation-free) ----------------
__device__ float    g_h[(size_t)BB * NN * FF];   // projected features h = x @ W^T
__device__ int      g_cnt[NN];                   // per-row edge counts
__device__ int      g_off[NN + 1];               // CSR row offsets
__device__ int      g_pos[NN];                   // scatter cursors
__device__ int      g_erow[EE];                  // edge rows as int32
__device__ int      g_ecol[EE];                  // edge cols as int32
__device__ int      g_scol[EE];                  // edge cols sorted by row
__device__ float    g_sval[EE];                  // edge vals sorted by row
__device__ int      g_bsum[NBLK];                // scan block sums
__device__ int      g_idx64;                     // 1 if edge indices are int64
__device__ uint32_t g_Bhi[8 * 16 * 32 * 2];      // W bf16-hi fragments, pre-swizzled
__device__ uint32_t g_Blo[8 * 16 * 32 * 2];      // W bf16-lo fragments

// ---------------- bf16 split helpers ------------------------------------------
__device__ __forceinline__ uint32_t pack_bf16_hi(float e0, float e1) {
    uint32_t r;
    asm("cvt.rn.bf16x2.f32 %0, %1, %2;" : "=r"(r) : "f"(e1), "f"(e0));
    return r;
}
__device__ __forceinline__ uint32_t pack_bf16_lo(uint32_t hi, float e0, float e1) {
    float h0 = __uint_as_float(hi << 16);
    float h1 = __uint_as_float(hi & 0xffff0000u);
    return pack_bf16_hi(e0 - h0, e1 - h1);
}

#define MMA16816(C, A0, A1, A2, A3, B0, B1)                                        \
    asm volatile("mma.sync.aligned.m16n8k16.row.col.f32.bf16.bf16.f32 "            \
                 "{%0,%1,%2,%3}, {%4,%5,%6,%7}, {%8,%9}, {%0,%1,%2,%3};"           \
                 : "+f"((C)[0]), "+f"((C)[1]), "+f"((C)[2]), "+f"((C)[3])          \
                 : "r"(A0), "r"(A1), "r"(A2), "r"(A3), "r"(B0), "r"(B1))

// ---------------- merged: prepB (blocks 0..15) + zero/detect (blocks 16..211) --
// prepB: B[k][n] = W[n*128+k]. Fragment (k_step, n_tile): lane l: n = nt*8 + (l>>2),
// reg rr: k0 = ks*16 + (l&3)*2 + rr*8, pack {W[n][k0], W[n][k0+1]} lo-first.
// zero: clear g_cnt. detect: int64 indices < 2^32 have every odd 32-bit word == 0.
__global__ void prep_kernel(const float* __restrict__ W,
                            const unsigned int* __restrict__ erow_words) {
    if (blockIdx.x < 16) {
        int t = blockIdx.x * 256 + threadIdx.x;   // 4096 threads
        int ks = t >> 9, nt = (t >> 5) & 15, lane = t & 31;
        int grp = lane >> 2, tig = lane & 3;
        int n = nt * 8 + grp;
        #pragma unroll
        for (int rr = 0; rr < 2; rr++) {
            int k0 = ks * 16 + tig * 2 + rr * 8;
            float e0 = W[n * FF + k0];
            float e1 = W[n * FF + k0 + 1];
            uint32_t hi = pack_bf16_hi(e0, e1);
            uint32_t lo = pack_bf16_lo(hi, e0, e1);
            int idx = ((ks * 16 + nt) * 32 + lane) * 2 + rr;
            g_Bhi[idx] = hi;
            g_Blo[idx] = lo;
        }
    } else {
        int i = (blockIdx.x - 16) * 256 + threadIdx.x;
        if (i < NN) g_cnt[i] = 0;
        if (i == 0) {
            int all0 = 1;
            for (int w = 1; w < 128; w += 2)
                if (erow_words[w] != 0u) all0 = 0;
            g_idx64 = all0;
        }
    }
}

// ---------------- GEMM: h = x @ W^T via split-bf16 tensor MMA ------------------
__global__ void __launch_bounds__(256) gemm_mma_kernel(const float* __restrict__ x) {
    extern __shared__ uint32_t sB[];
    uint32_t* sBhi = sB;           // [8][16][32][2]
    uint32_t* sBlo = sB + 8192;

    for (int i = threadIdx.x; i < 8192; i += 256) {
        sBhi[i] = g_Bhi[i];
        sBlo[i] = g_Blo[i];
    }
    __syncthreads();

    const int lane = threadIdx.x & 31;
    const int warp = threadIdx.x >> 5;
    const int grp = lane >> 2, tig = lane & 3;
    const int nwarps = gridDim.x * 8;

    for (int tile = blockIdx.x * 8 + warp; tile < NTILES; tile += nwarps) {
        const int row0 = tile * 16;
        const float* xr0 = x + (size_t)(row0 + grp) * FF;       // rows grp, grp+8
        const float* xr1 = x + (size_t)(row0 + grp + 8) * FF;

        float acc[16][4];
        #pragma unroll
        for (int nt = 0; nt < 16; nt++)
            #pragma unroll
            for (int j = 0; j < 4; j++) acc[nt][j] = 0.0f;

        #pragma unroll 2
        for (int ks = 0; ks < 8; ks++) {
            const int c0 = ks * 16 + tig * 2;
            float2 f0 = *(const float2*)(xr0 + c0);
            float2 f1 = *(const float2*)(xr1 + c0);
            float2 f2 = *(const float2*)(xr0 + c0 + 8);
            float2 f3 = *(const float2*)(xr1 + c0 + 8);

            uint32_t ah0 = pack_bf16_hi(f0.x, f0.y), al0 = pack_bf16_lo(ah0, f0.x, f0.y);
            uint32_t ah1 = pack_bf16_hi(f1.x, f1.y), al1 = pack_bf16_lo(ah1, f1.x, f1.y);
            uint32_t ah2 = pack_bf16_hi(f2.x, f2.y), al2 = pack_bf16_lo(ah2, f2.x, f2.y);
            uint32_t ah3 = pack_bf16_hi(f3.x, f3.y), al3 = pack_bf16_lo(ah3, f3.x, f3.y);

            const uint32_t* bh = sBhi + (ks * 16 * 32 + lane) * 2;
            const uint32_t* bl = sBlo + (ks * 16 * 32 + lane) * 2;
            #pragma unroll
            for (int nt = 0; nt < 16; nt++) {
                uint32_t b0h = bh[nt * 64], b1h = bh[nt * 64 + 1];
                uint32_t b0l = bl[nt * 64], b1l = bl[nt * 64 + 1];
                MMA16816(acc[nt], ah0, ah1, ah2, ah3, b0h, b1h);  // hi*hi
                MMA16816(acc[nt], ah0, ah1, ah2, ah3, b0l, b1l);  // hi*lo
                MMA16816(acc[nt], al0, al1, al2, al3, b0h, b1h);  // lo*hi
            }
        }

        float* h0 = g_h + (size_t)(row0 + grp) * FF;
        float* h1 = g_h + (size_t)(row0 + grp + 8) * FF;
        #pragma unroll
        for (int nt = 0; nt < 16; nt++) {
            int col = nt * 8 + tig * 2;
            *(float2*)(h0 + col) = make_float2(acc[nt][0], acc[nt][1]);
            *(float2*)(h1 + col) = make_float2(acc[nt][2], acc[nt][3]);
        }
    }
}

// ---------------- index convert + histogram: 2 edges/thread --------------------
__global__ void convert_kernel(const void* __restrict__ erow,
                               const void* __restrict__ ecol) {
    int t = blockIdx.x * blockDim.x + threadIdx.x;
    int e = t * 2;
    if (e >= EE) return;
    int r0, r1, c0, c1;
    if (g_idx64) {
        ulonglong2 R = ((const ulonglong2*)erow)[t];
        ulonglong2 C = ((const ulonglong2*)ecol)[t];
        r0 = (int)R.x; r1 = (int)R.y;
        c0 = (int)C.x; c1 = (int)C.y;
    } else {
        int2 R = ((const int2*)erow)[t];
        int2 C = ((const int2*)ecol)[t];
        r0 = R.x; r1 = R.y;
        c0 = C.x; c1 = C.y;
    }
    *(int2*)(g_erow + e) = make_int2(r0, r1);
    *(int2*)(g_ecol + e) = make_int2(c0, c1);
    atomicAdd(&g_cnt[r0], 1);
    atomicAdd(&g_cnt[r1], 1);
}

// ---------------- CSR build ----------------------------------------------------
// inclusive scan per 1024-chunk -> g_off (temp), block totals -> g_bsum
__global__ void scanA_kernel() {
    __shared__ int smv[1024];
    int i = blockIdx.x * 1024 + threadIdx.x;
    int v = (i < NN) ? g_cnt[i] : 0;
    smv[threadIdx.x] = v;
    __syncthreads();
    for (int d = 1; d < 1024; d <<= 1) {
        int t = (threadIdx.x >= d) ? smv[threadIdx.x - d] : 0;
        __syncthreads();
        smv[threadIdx.x] += t;
        __syncthreads();
    }
    if (i < NN) g_off[i] = smv[threadIdx.x];
    if (threadIdx.x == 1023) g_bsum[blockIdx.x] = smv[1023];
}

// per-block prefix of g_bsum computed by thread 0 (<=48 adds), then finalize
// exclusive offsets + cursors. Also closes CSR (g_off[NN] = EE).
__global__ void scanC_kernel() {
    __shared__ int sprefix;
    if (threadIdx.x == 0) {
        int run = 0;
        for (int b = 0; b < (int)blockIdx.x; b++) run += g_bsum[b];
        sprefix = run;
    }
    __syncthreads();
    int i = blockIdx.x * 1024 + threadIdx.x;
    if (i < NN) {
        int excl = g_off[i] - g_cnt[i] + sprefix;
        g_off[i] = excl;
        g_pos[i] = excl;
    }
    if (i == 0) g_off[NN] = EE;
}

__global__ void scatter_kernel(const float* __restrict__ evals) {
    int t = blockIdx.x * blockDim.x + threadIdx.x;
    int e = t * 2;
    if (e >= EE) return;
    int2   R = *(const int2*)(g_erow + e);
    int2   C = *(const int2*)(g_ecol + e);
    float2 V = *(const float2*)(evals + e);
    int p0 = atomicAdd(&g_pos[R.x], 1);
    g_scol[p0] = C.x;
    g_sval[p0] = V.x;
    int p1 = atomicAdd(&g_pos[R.y], 1);
    g_scol[p1] = C.y;
    g_sval[p1] = V.y;
}

// ---------------- SpMM: one warp per row, all 4 batches fused -------------------
// Index/value loads read once per edge; 8 independent LDG.128 in flight per
// 2-edge unroll step keeps the LTS pipe saturated.
__global__ void __launch_bounds__(256) spmm_kernel(float* __restrict__ out) {
    int wg = (blockIdx.x * blockDim.x + threadIdx.x) >> 5;
    int lane = threadIdx.x & 31;
    if (wg >= NN) return;

    int s = g_off[wg];
    int e = g_off[wg + 1];
    const float* h0 = g_h;
    const float* h1 = g_h + HB;
    const float* h2 = g_h + 2 * HB;
    const float* h3 = g_h + 3 * HB;

    float4 a0 = {0,0,0,0}, a1 = {0,0,0,0}, a2 = {0,0,0,0}, a3 = {0,0,0,0};

    int i = s;
    for (; i + 1 < e; i += 2) {
        int   c0 = g_scol[i],   c1 = g_scol[i + 1];
        float v0 = g_sval[i],   v1 = g_sval[i + 1];
        size_t o0 = (size_t)c0 * FF, o1 = (size_t)c1 * FF;
        float4 u0 = ((const float4*)(h0 + o0))[lane];
        float4 u1 = ((const float4*)(h1 + o0))[lane];
        float4 u2 = ((const float4*)(h2 + o0))[lane];
        float4 u3 = ((const float4*)(h3 + o0))[lane];
        float4 w0 = ((const float4*)(h0 + o1))[lane];
        float4 w1 = ((const float4*)(h1 + o1))[lane];
        float4 w2 = ((const float4*)(h2 + o1))[lane];
        float4 w3 = ((const float4*)(h3 + o1))[lane];
        a0.x += v0 * u0.x + v1 * w0.x;  a0.y += v0 * u0.y + v1 * w0.y;
        a0.z += v0 * u0.z + v1 * w0.z;  a0.w += v0 * u0.w + v1 * w0.w;
        a1.x += v0 * u1.x + v1 * w1.x;  a1.y += v0 * u1.y + v1 * w1.y;
        a1.z += v0 * u1.z + v1 * w1.z;  a1.w += v0 * u1.w + v1 * w1.w;
        a2.x += v0 * u2.x + v1 * w2.x;  a2.y += v0 * u2.y + v1 * w2.y;
        a2.z += v0 * u2.z + v1 * w2.z;  a2.w += v0 * u2.w + v1 * w2.w;
        a3.x += v0 * u3.x + v1 * w3.x;  a3.y += v0 * u3.y + v1 * w3.y;
        a3.z += v0 * u3.z + v1 * w3.z;  a3.w += v0 * u3.w + v1 * w3.w;
    }
    if (i < e) {
        int   c = g_scol[i];
        float v = g_sval[i];
        size_t o = (size_t)c * FF;
        float4 u0 = ((const float4*)(h0 + o))[lane];
        float4 u1 = ((const float4*)(h1 + o))[lane];
        float4 u2 = ((const float4*)(h2 + o))[lane];
        float4 u3 = ((const float4*)(h3 + o))[lane];
        a0.x += v * u0.x; a0.y += v * u0.y; a0.z += v * u0.z; a0.w += v * u0.w;
        a1.x += v * u1.x; a1.y += v * u1.y; a1.z += v * u1.z; a1.w += v * u1.w;
        a2.x += v * u2.x; a2.y += v * u2.y; a2.z += v * u2.z; a2.w += v * u2.w;
        a3.x += v * u3.x; a3.y += v * u3.y; a3.z += v * u3.z; a3.w += v * u3.w;
    }

    size_t ro = (size_t)wg * FF;
    ((float4*)(out + ro))[lane]          = a0;
    ((float4*)(out + HB + ro))[lane]     = a1;
    ((float4*)(out + 2 * HB + ro))[lane] = a2;
    ((float4*)(out + 3 * HB + ro))[lane] = a3;
}

// ---------------- launch --------------------------------------------------------
extern "C" void kernel_launch(void* const* d_in, const int* in_sizes, int n_in,
                              void* d_out, int out_size) {
    const float* x     = (const float*)d_in[0];
    const float* W     = (const float*)d_in[1];
    const void*  erow  = d_in[2];
    const void*  ecol  = d_in[3];
    const float* evals = (const float*)d_in[4];
    float*       out   = (float*)d_out;

    const int SMEM_B = 2 * 8192 * (int)sizeof(uint32_t);  // 64 KB
    cudaFuncSetAttribute(gemm_mma_kernel, cudaFuncAttributeMaxDynamicSharedMemorySize, SMEM_B);

    prep_kernel<<<16 + (NN + 255) / 256, 256>>>(W, (const unsigned int*)erow);
    gemm_mma_kernel<<<296, 256, SMEM_B>>>(x);

    convert_kernel<<<(EE / 2 + 255) / 256, 256>>>(erow, ecol);
    scanA_kernel<<<NBLK, 1024>>>();
    scanC_kernel<<<NBLK, 1024>>>();
    scatter_kernel<<<(EE / 2 + 255) / 256, 256>>>(evals);

    spmm_kernel<<<(NN * 32 + 255) / 256, 256>>>(out);
}

// round 8
// speedup vs baseline: 1.1962x; 1.1962x over previous
#include <cuda_runtime.h>
#include <cstdint>

#define BB 4
#define NN 50000
#define EE 800000
#define FF 128
#define NBLK 49           // ceil(NN/1024)
#define NTILES 12500      // 16-row warp tiles (200000/16)
#define HB ((size_t)NN * FF)

// ---------------- scratch (__device__ globals: allocation-free) ----------------
__device__ float    g_h[(size_t)BB * NN * FF];   // projected features h = x @ W^T
__device__ int      g_cnt[NN];                   // per-row edge counts
__device__ int      g_off[NN + 1];               // CSR row offsets
__device__ int      g_pos[NN];                   // scatter cursors
__device__ int      g_erow[EE];                  // edge rows as int32
__device__ int      g_ecol[EE];                  // edge cols as int32
__device__ int      g_scol[EE];                  // edge cols sorted by row
__device__ float    g_sval[EE];                  // edge vals sorted by row
__device__ int      g_bsum[NBLK];                // scan block sums
__device__ int      g_idx64;                     // 1 if edge indices are int64
__device__ uint32_t g_Bhi[8 * 16 * 32 * 2];      // W bf16-hi fragments, pre-swizzled
__device__ uint32_t g_Blo[8 * 16 * 32 * 2];      // W bf16-lo fragments

// ---------------- bf16 split helpers ------------------------------------------
__device__ __forceinline__ uint32_t pack_bf16_hi(float e0, float e1) {
    uint32_t r;
    asm("cvt.rn.bf16x2.f32 %0, %1, %2;" : "=r"(r) : "f"(e1), "f"(e0));
    return r;
}
__device__ __forceinline__ uint32_t pack_bf16_lo(uint32_t hi, float e0, float e1) {
    float h0 = __uint_as_float(hi << 16);
    float h1 = __uint_as_float(hi & 0xffff0000u);
    return pack_bf16_hi(e0 - h0, e1 - h1);
}

#define MMA16816(C, A0, A1, A2, A3, B0, B1)                                        \
    asm volatile("mma.sync.aligned.m16n8k16.row.col.f32.bf16.bf16.f32 "            \
                 "{%0,%1,%2,%3}, {%4,%5,%6,%7}, {%8,%9}, {%0,%1,%2,%3};"           \
                 : "+f"((C)[0]), "+f"((C)[1]), "+f"((C)[2]), "+f"((C)[3])          \
                 : "r"(A0), "r"(A1), "r"(A2), "r"(A3), "r"(B0), "r"(B1))

// ---------------- merged: prepB (blocks 0..15) + zero/detect (blocks 16..) -----
__global__ void prep_kernel(const float* __restrict__ W,
                            const unsigned int* __restrict__ erow_words) {
    if (blockIdx.x < 16) {
        int t = blockIdx.x * 256 + threadIdx.x;   // 4096 threads
        int ks = t >> 9, nt = (t >> 5) & 15, lane = t & 31;
        int grp = lane >> 2, tig = lane & 3;
        int n = nt * 8 + grp;
        #pragma unroll
        for (int rr = 0; rr < 2; rr++) {
            int k0 = ks * 16 + tig * 2 + rr * 8;
            float e0 = W[n * FF + k0];
            float e1 = W[n * FF + k0 + 1];
            uint32_t hi = pack_bf16_hi(e0, e1);
            uint32_t lo = pack_bf16_lo(hi, e0, e1);
            int idx = ((ks * 16 + nt) * 32 + lane) * 2 + rr;
            g_Bhi[idx] = hi;
            g_Blo[idx] = lo;
        }
    } else {
        int i = (blockIdx.x - 16) * 256 + threadIdx.x;
        if (i < NN) g_cnt[i] = 0;
        if (i == 0) {
            // int64 indices < 2^32 have every odd 32-bit word == 0
            int all0 = 1;
            for (int w = 1; w < 128; w += 2)
                if (erow_words[w] != 0u) all0 = 0;
            g_idx64 = all0;
        }
    }
}

// ---------------- GEMM: h = x @ W^T via split-bf16 tensor MMA ------------------
__global__ void __launch_bounds__(256) gemm_mma_kernel(const float* __restrict__ x) {
    extern __shared__ uint32_t sB[];
    uint32_t* sBhi = sB;           // [8][16][32][2]
    uint32_t* sBlo = sB + 8192;

    for (int i = threadIdx.x; i < 8192; i += 256) {
        sBhi[i] = g_Bhi[i];
        sBlo[i] = g_Blo[i];
    }
    __syncthreads();

    const int lane = threadIdx.x & 31;
    const int warp = threadIdx.x >> 5;
    const int grp = lane >> 2, tig = lane & 3;
    const int nwarps = gridDim.x * 8;

    for (int tile = blockIdx.x * 8 + warp; tile < NTILES; tile += nwarps) {
        const int row0 = tile * 16;
        const float* xr0 = x + (size_t)(row0 + grp) * FF;       // rows grp, grp+8
        const float* xr1 = x + (size_t)(row0 + grp + 8) * FF;

        float acc[16][4];
        #pragma unroll
        for (int nt = 0; nt < 16; nt++)
            #pragma unroll
            for (int j = 0; j < 4; j++) acc[nt][j] = 0.0f;

        #pragma unroll 2
        for (int ks = 0; ks < 8; ks++) {
            const int c0 = ks * 16 + tig * 2;
            float2 f0 = *(const float2*)(xr0 + c0);
            float2 f1 = *(const float2*)(xr1 + c0);
            float2 f2 = *(const float2*)(xr0 + c0 + 8);
            float2 f3 = *(const float2*)(xr1 + c0 + 8);

            uint32_t ah0 = pack_bf16_hi(f0.x, f0.y), al0 = pack_bf16_lo(ah0, f0.x, f0.y);
            uint32_t ah1 = pack_bf16_hi(f1.x, f1.y), al1 = pack_bf16_lo(ah1, f1.x, f1.y);
            uint32_t ah2 = pack_bf16_hi(f2.x, f2.y), al2 = pack_bf16_lo(ah2, f2.x, f2.y);
            uint32_t ah3 = pack_bf16_hi(f3.x, f3.y), al3 = pack_bf16_lo(ah3, f3.x, f3.y);

            const uint32_t* bh = sBhi + (ks * 16 * 32 + lane) * 2;
            const uint32_t* bl = sBlo + (ks * 16 * 32 + lane) * 2;
            #pragma unroll
            for (int nt = 0; nt < 16; nt++) {
                uint32_t b0h = bh[nt * 64], b1h = bh[nt * 64 + 1];
                uint32_t b0l = bl[nt * 64], b1l = bl[nt * 64 + 1];
                MMA16816(acc[nt], ah0, ah1, ah2, ah3, b0h, b1h);  // hi*hi
                MMA16816(acc[nt], ah0, ah1, ah2, ah3, b0l, b1l);  // hi*lo
                MMA16816(acc[nt], al0, al1, al2, al3, b0h, b1h);  // lo*hi
            }
        }

        float* h0 = g_h + (size_t)(row0 + grp) * FF;
        float* h1 = g_h + (size_t)(row0 + grp + 8) * FF;
        #pragma unroll
        for (int nt = 0; nt < 16; nt++) {
            int col = nt * 8 + tig * 2;
            *(float2*)(h0 + col) = make_float2(acc[nt][0], acc[nt][1]);
            *(float2*)(h1 + col) = make_float2(acc[nt][2], acc[nt][3]);
        }
    }
}

// ---------------- index convert + histogram: 2 edges/thread --------------------
__global__ void convert_kernel(const void* __restrict__ erow,
                               const void* __restrict__ ecol) {
    int t = blockIdx.x * blockDim.x + threadIdx.x;
    int e = t * 2;
    if (e >= EE) return;
    int r0, r1, c0, c1;
    if (g_idx64) {
        ulonglong2 R = ((const ulonglong2*)erow)[t];
        ulonglong2 C = ((const ulonglong2*)ecol)[t];
        r0 = (int)R.x; r1 = (int)R.y;
        c0 = (int)C.x; c1 = (int)C.y;
    } else {
        int2 R = ((const int2*)erow)[t];
        int2 C = ((const int2*)ecol)[t];
        r0 = R.x; r1 = R.y;
        c0 = C.x; c1 = C.y;
    }
    *(int2*)(g_erow + e) = make_int2(r0, r1);
    *(int2*)(g_ecol + e) = make_int2(c0, c1);
    atomicAdd(&g_cnt[r0], 1);
    atomicAdd(&g_cnt[r1], 1);
}

// ---------------- CSR build ----------------------------------------------------
__global__ void scanA_kernel() {
    __shared__ int smv[1024];
    int i = blockIdx.x * 1024 + threadIdx.x;
    int v = (i < NN) ? g_cnt[i] : 0;
    smv[threadIdx.x] = v;
    __syncthreads();
    for (int d = 1; d < 1024; d <<= 1) {
        int t = (threadIdx.x >= d) ? smv[threadIdx.x - d] : 0;
        __syncthreads();
        smv[threadIdx.x] += t;
        __syncthreads();
    }
    if (i < NN) g_off[i] = smv[threadIdx.x];
    if (threadIdx.x == 1023) g_bsum[blockIdx.x] = smv[1023];
}

// per-block prefix of g_bsum by thread 0 (<=48 adds), finalize offsets + cursors
__global__ void scanC_kernel() {
    __shared__ int sprefix;
    if (threadIdx.x == 0) {
        int run = 0;
        for (int b = 0; b < (int)blockIdx.x; b++) run += g_bsum[b];
        sprefix = run;
    }
    __syncthreads();
    int i = blockIdx.x * 1024 + threadIdx.x;
    if (i < NN) {
        int excl = g_off[i] - g_cnt[i] + sprefix;
        g_off[i] = excl;
        g_pos[i] = excl;
    }
    if (i == 0) g_off[NN] = EE;
}

__global__ void scatter_kernel(const float* __restrict__ evals) {
    int t = blockIdx.x * blockDim.x + threadIdx.x;
    int e = t * 2;
    if (e >= EE) return;
    int2   R = *(const int2*)(g_erow + e);
    int2   C = *(const int2*)(g_ecol + e);
    float2 V = *(const float2*)(evals + e);
    int p0 = atomicAdd(&g_pos[R.x], 1);
    g_scol[p0] = C.x;
    g_sval[p0] = V.x;
    int p1 = atomicAdd(&g_pos[R.y], 1);
    g_scol[p1] = C.y;
    g_sval[p1] = V.y;
}

// ---------------- SpMM: one warp per (batch,row), batch-major -------------------
// Concurrent warps share one batch's h (25.6 MB, L2-resident). 4-edge unroll
// keeps 4 independent LDG.128 in flight per warp.
__global__ void __launch_bounds__(256) spmm_kernel(float* __restrict__ out) {
    int wg = (blockIdx.x * blockDim.x + threadIdx.x) >> 5;
    int lane = threadIdx.x & 31;
    if (wg >= BB * NN) return;
    int b = wg / NN;
    int r = wg - b * NN;

    int s = g_off[r];
    int e = g_off[r + 1];
    const float* hb = g_h + (size_t)b * HB;

    float4 acc = {0, 0, 0, 0};
    int i = s;
    for (; i + 3 < e; i += 4) {
        int   c0 = g_scol[i],     c1 = g_scol[i + 1];
        int   c2 = g_scol[i + 2], c3 = g_scol[i + 3];
        float v0 = g_sval[i],     v1 = g_sval[i + 1];
        float v2 = g_sval[i + 2], v3 = g_sval[i + 3];
        float4 u0 = ((const float4*)(hb + (size_t)c0 * FF))[lane];
        float4 u1 = ((const float4*)(hb + (size_t)c1 * FF))[lane];
        float4 u2 = ((const float4*)(hb + (size_t)c2 * FF))[lane];
        float4 u3 = ((const float4*)(hb + (size_t)c3 * FF))[lane];
        acc.x += v0 * u0.x + v1 * u1.x + v2 * u2.x + v3 * u3.x;
        acc.y += v0 * u0.y + v1 * u1.y + v2 * u2.y + v3 * u3.y;
        acc.z += v0 * u0.z + v1 * u1.z + v2 * u2.z + v3 * u3.z;
        acc.w += v0 * u0.w + v1 * u1.w + v2 * u2.w + v3 * u3.w;
    }
    for (; i < e; i++) {
        int   c = g_scol[i];
        float v = g_sval[i];
        float4 hv = ((const float4*)(hb + (size_t)c * FF))[lane];
        acc.x += v * hv.x;
        acc.y += v * hv.y;
        acc.z += v * hv.z;
        acc.w += v * hv.w;
    }
    ((float4*)(out + ((size_t)b * NN + r) * FF))[lane] = acc;
}

// ---------------- launch --------------------------------------------------------
extern "C" void kernel_launch(void* const* d_in, const int* in_sizes, int n_in,
                              void* d_out, int out_size) {
    const float* x     = (const float*)d_in[0];
    const float* W     = (const float*)d_in[1];
    const void*  erow  = d_in[2];
    const void*  ecol  = d_in[3];
    const float* evals = (const float*)d_in[4];
    float*       out   = (float*)d_out;

    const int SMEM_B = 2 * 8192 * (int)sizeof(uint32_t);  // 64 KB
    cudaFuncSetAttribute(gemm_mma_kernel, cudaFuncAttributeMaxDynamicSharedMemorySize, SMEM_B);

    prep_kernel<<<16 + (NN + 255) / 256, 256>>>(W, (const unsigned int*)erow);
    gemm_mma_kernel<<<296, 256, SMEM_B>>>(x);

    convert_kernel<<<(EE / 2 + 255) / 256, 256>>>(erow, ecol);
    scanA_kernel<<<NBLK, 1024>>>();
    scanC_kernel<<<NBLK, 1024>>>();
    scatter_kernel<<<(EE / 2 + 255) / 256, 256>>>(evals);

    spmm_kernel<<<(BB * NN * 32 + 255) / 256, 256>>>(out);
}

// round 10
// speedup vs baseline: 1.3941x; 1.1654x over previous
#include <cuda_runtime.h>
#include <cuda_fp16.h>
#include <cstdint>

#define BB 4
#define NN 50000
#define EE 800000
#define FF 128
#define NBLK 49           // ceil(NN/1024)
#define NTILES 12500      // 16-row warp tiles (200000/16)
#define HB ((size_t)NN * FF)
#define GEMM_BLOCKS 296
#define CONV_BLOCKS ((EE / 2 + 255) / 256)   // 1563

// ---------------- scratch (__device__ globals: allocation-free) ----------------
__device__ __half   g_hh[(size_t)BB * NN * FF]; // projected features, fp16
__device__ int      g_cnt[NN];                  // per-row edge counts
__device__ int      g_off[NN + 1];              // CSR row offsets
__device__ int      g_pos[NN];                  // scatter cursors
__device__ int      g_erow[EE];                 // edge rows as int32
__device__ int      g_ecol[EE];                 // edge cols as int32
__device__ int      g_scol[EE];                 // edge cols sorted by row
__device__ float    g_sval[EE];                 // edge vals sorted by row
__device__ int      g_bsum[NBLK];               // scan block sums
__device__ int      g_sync;                     // scan grid barrier counter
__device__ int      g_idx64;                    // 1 if edge indices are int64
__device__ uint32_t g_Bhi[8 * 16 * 32 * 2];     // W bf16-hi fragments, pre-swizzled
__device__ uint32_t g_Blo[8 * 16 * 32 * 2];     // W bf16-lo fragments

// ---------------- bf16 split helpers ------------------------------------------
__device__ __forceinline__ uint32_t pack_bf16_hi(float e0, float e1) {
    uint32_t r;
    asm("cvt.rn.bf16x2.f32 %0, %1, %2;" : "=r"(r) : "f"(e1), "f"(e0));
    return r;
}
__device__ __forceinline__ uint32_t pack_bf16_lo(uint32_t hi, float e0, float e1) {
    float h0 = __uint_as_float(hi << 16);
    float h1 = __uint_as_float(hi & 0xffff0000u);
    return pack_bf16_hi(e0 - h0, e1 - h1);
}

#define MMA16816(C, A0, A1, A2, A3, B0, B1)                                        \
    asm volatile("mma.sync.aligned.m16n8k16.row.col.f32.bf16.bf16.f32 "            \
                 "{%0,%1,%2,%3}, {%4,%5,%6,%7}, {%8,%9}, {%0,%1,%2,%3};"           \
                 : "+f"((C)[0]), "+f"((C)[1]), "+f"((C)[2]), "+f"((C)[3])          \
                 : "r"(A0), "r"(A1), "r"(A2), "r"(A3), "r"(B0), "r"(B1))

// ---------------- merged: prepB (blocks 0..15) + zero/detect (blocks 16..) -----
__global__ void prep_kernel(const float* __restrict__ W,
                            const unsigned int* __restrict__ erow_words) {
    if (blockIdx.x < 16) {
        int t = blockIdx.x * 256 + threadIdx.x;   // 4096 threads
        int ks = t >> 9, nt = (t >> 5) & 15, lane = t & 31;
        int grp = lane >> 2, tig = lane & 3;
        int n = nt * 8 + grp;
        #pragma unroll
        for (int rr = 0; rr < 2; rr++) {
            int k0 = ks * 16 + tig * 2 + rr * 8;
            float e0 = W[n * FF + k0];
            float e1 = W[n * FF + k0 + 1];
            uint32_t hi = pack_bf16_hi(e0, e1);
            uint32_t lo = pack_bf16_lo(hi, e0, e1);
            int idx = ((ks * 16 + nt) * 32 + lane) * 2 + rr;
            g_Bhi[idx] = hi;
            g_Blo[idx] = lo;
        }
    } else {
        int i = (blockIdx.x - 16) * 256 + threadIdx.x;
        if (i < NN) g_cnt[i] = 0;
        if (i == 0) {
            // int64 indices < 2^32 have every odd 32-bit word == 0
            int all0 = 1;
            for (int w = 1; w < 128; w += 2)
                if (erow_words[w] != 0u) all0 = 0;
            g_idx64 = all0;
            g_sync = 0;
        }
    }
}

// ---------------- GEMM (blocks < GEMM_BLOCKS) + index convert (rest) -----------
// GEMM: h = x @ W^T via split-bf16 tensor MMA, result stored fp16.
// Convert: widen edge indices to int32 + histogram (hidden under GEMM time).
__global__ void __launch_bounds__(256) gemm_conv_kernel(const float* __restrict__ x,
                                                        const void* __restrict__ erow,
                                                        const void* __restrict__ ecol) {
    if (blockIdx.x >= GEMM_BLOCKS) {
        int t = (blockIdx.x - GEMM_BLOCKS) * 256 + threadIdx.x;
        int e = t * 2;
        if (e >= EE) return;
        int r0, r1, c0, c1;
        if (g_idx64) {
            ulonglong2 R = ((const ulonglong2*)erow)[t];
            ulonglong2 C = ((const ulonglong2*)ecol)[t];
            r0 = (int)R.x; r1 = (int)R.y;
            c0 = (int)C.x; c1 = (int)C.y;
        } else {
            int2 R = ((const int2*)erow)[t];
            int2 C = ((const int2*)ecol)[t];
            r0 = R.x; r1 = R.y;
            c0 = C.x; c1 = C.y;
        }
        *(int2*)(g_erow + e) = make_int2(r0, r1);
        *(int2*)(g_ecol + e) = make_int2(c0, c1);
        atomicAdd(&g_cnt[r0], 1);
        atomicAdd(&g_cnt[r1], 1);
        return;
    }

    extern __shared__ uint32_t sB[];
    uint32_t* sBhi = sB;           // [8][16][32][2]
    uint32_t* sBlo = sB + 8192;

    for (int i = threadIdx.x; i < 8192; i += 256) {
        sBhi[i] = g_Bhi[i];
        sBlo[i] = g_Blo[i];
    }
    __syncthreads();

    const int lane = threadIdx.x & 31;
    const int warp = threadIdx.x >> 5;
    const int grp = lane >> 2, tig = lane & 3;
    const int nwarps = GEMM_BLOCKS * 8;

    for (int tile = blockIdx.x * 8 + warp; tile < NTILES; tile += nwarps) {
        const int row0 = tile * 16;
        const float* xr0 = x + (size_t)(row0 + grp) * FF;       // rows grp, grp+8
        const float* xr1 = x + (size_t)(row0 + grp + 8) * FF;

        float acc[16][4];
        #pragma unroll
        for (int nt = 0; nt < 16; nt++)
            #pragma unroll
            for (int j = 0; j < 4; j++) acc[nt][j] = 0.0f;

        #pragma unroll 2
        for (int ks = 0; ks < 8; ks++) {
            const int c0 = ks * 16 + tig * 2;
            float2 f0 = *(const float2*)(xr0 + c0);
            float2 f1 = *(const float2*)(xr1 + c0);
            float2 f2 = *(const float2*)(xr0 + c0 + 8);
            float2 f3 = *(const float2*)(xr1 + c0 + 8);

            uint32_t ah0 = pack_bf16_hi(f0.x, f0.y), al0 = pack_bf16_lo(ah0, f0.x, f0.y);
            uint32_t ah1 = pack_bf16_hi(f1.x, f1.y), al1 = pack_bf16_lo(ah1, f1.x, f1.y);
            uint32_t ah2 = pack_bf16_hi(f2.x, f2.y), al2 = pack_bf16_lo(ah2, f2.x, f2.y);
            uint32_t ah3 = pack_bf16_hi(f3.x, f3.y), al3 = pack_bf16_lo(ah3, f3.x, f3.y);

            const uint32_t* bh = sBhi + (ks * 16 * 32 + lane) * 2;
            const uint32_t* bl = sBlo + (ks * 16 * 32 + lane) * 2;
            #pragma unroll
            for (int nt = 0; nt < 16; nt++) {
                uint32_t b0h = bh[nt * 64], b1h = bh[nt * 64 + 1];
                uint32_t b0l = bl[nt * 64], b1l = bl[nt * 64 + 1];
                MMA16816(acc[nt], ah0, ah1, ah2, ah3, b0h, b1h);  // hi*hi
                MMA16816(acc[nt], ah0, ah1, ah2, ah3, b0l, b1l);  // hi*lo
                MMA16816(acc[nt], al0, al1, al2, al3, b0h, b1h);  // lo*hi
            }
        }

        // store fp16: c0,c1 -> (row grp, col nt*8+tig*2); c2,c3 -> row grp+8
        __half* h0 = g_hh + (size_t)(row0 + grp) * FF;
        __half* h1 = g_hh + (size_t)(row0 + grp + 8) * FF;
        #pragma unroll
        for (int nt = 0; nt < 16; nt++) {
            int col = nt * 8 + tig * 2;
            *(__half2*)(h0 + col) = __float22half2_rn(make_float2(acc[nt][0], acc[nt][1]));
            *(__half2*)(h1 + col) = __float22half2_rn(make_float2(acc[nt][2], acc[nt][3]));
        }
    }
}

// ---------------- fused CSR scan: local scan + grid barrier + finalize ---------
// 49 blocks, all chip-resident, so the atomic spin barrier is safe.
__global__ void scan_kernel() {
    __shared__ int smv[1024];
    int i = blockIdx.x * 1024 + threadIdx.x;
    int cnt = (i < NN) ? g_cnt[i] : 0;
    smv[threadIdx.x] = cnt;
    __syncthreads();
    for (int d = 1; d < 1024; d <<= 1) {
        int t = (threadIdx.x >= d) ? smv[threadIdx.x - d] : 0;
        __syncthreads();
        smv[threadIdx.x] += t;
        __syncthreads();
    }
    int incl = smv[threadIdx.x];
    if (threadIdx.x == 1023) g_bsum[blockIdx.x] = incl;

    // grid barrier
    __threadfence();
    __syncthreads();
    if (threadIdx.x == 0) {
        atomicAdd(&g_sync, 1);
        while (atomicAdd(&g_sync, 0) < NBLK) { }
    }
    __syncthreads();

    __shared__ int sprefix;
    if (threadIdx.x == 0) {
        int run = 0;
        for (int b = 0; b < (int)blockIdx.x; b++) run += g_bsum[b];
        sprefix = run;
    }
    __syncthreads();
    if (i < NN) {
        int excl = incl - cnt + sprefix;
        g_off[i] = excl;
        g_pos[i] = excl;
    }
    if (i == 0) g_off[NN] = EE;
}

__global__ void scatter_kernel(const float* __restrict__ evals) {
    int t = blockIdx.x * blockDim.x + threadIdx.x;
    int e = t * 2;
    if (e >= EE) return;
    int2   R = *(const int2*)(g_erow + e);
    int2   C = *(const int2*)(g_ecol + e);
    float2 V = *(const float2*)(evals + e);
    int p0 = atomicAdd(&g_pos[R.x], 1);
    g_scol[p0] = C.x;
    g_sval[p0] = V.x;
    int p1 = atomicAdd(&g_pos[R.y], 1);
    g_scol[p1] = C.y;
    g_sval[p1] = V.y;
}

// ---------------- SpMM: one warp per (batch,row), batch-major, fp16 gathers ----
// Each lane owns 4 columns (4 halfs = 8B load). 4-edge unroll: 4 independent
// LDG.64 gathers in flight; per-batch h footprint 12.8 MB stays L2-resident.
__global__ void __launch_bounds__(256) spmm_kernel(float* __restrict__ out) {
    int wg = (blockIdx.x * blockDim.x + threadIdx.x) >> 5;
    int lane = threadIdx.x & 31;
    if (wg >= BB * NN) return;
    int b = wg / NN;
    int r = wg - b * NN;

    int s = g_off[r];
    int e = g_off[r + 1];
    const __half* hb = g_hh + (size_t)b * HB + lane * 4;

    float4 acc = {0, 0, 0, 0};
    int i = s;
    for (; i + 3 < e; i += 4) {
        int   c0 = g_scol[i],     c1 = g_scol[i + 1];
        int   c2 = g_scol[i + 2], c3 = g_scol[i + 3];
        float v0 = g_sval[i],     v1 = g_sval[i + 1];
        float v2 = g_sval[i + 2], v3 = g_sval[i + 3];
        __half2 p0a = *(const __half2*)(hb + (size_t)c0 * FF);
        __half2 p0b = *(const __half2*)(hb + (size_t)c0 * FF + 2);
        __half2 p1a = *(const __half2*)(hb + (size_t)c1 * FF);
        __half2 p1b = *(const __half2*)(hb + (size_t)c1 * FF + 2);
        __half2 p2a = *(const __half2*)(hb + (size_t)c2 * FF);
        __half2 p2b = *(const __half2*)(hb + (size_t)c2 * FF + 2);
        __half2 p3a = *(const __half2*)(hb + (size_t)c3 * FF);
        __half2 p3b = *(const __half2*)(hb + (size_t)c3 * FF + 2);
        float2 f0a = __half22float2(p0a), f0b = __half22float2(p0b);
        float2 f1a = __half22float2(p1a), f1b = __half22float2(p1b);
        float2 f2a = __half22float2(p2a), f2b = __half22float2(p2b);
        float2 f3a = __half22float2(p3a), f3b = __half22float2(p3b);
        acc.x += v0 * f0a.x + v1 * f1a.x + v2 * f2a.x + v3 * f3a.x;
        acc.y += v0 * f0a.y + v1 * f1a.y + v2 * f2a.y + v3 * f3a.y;
        acc.z += v0 * f0b.x + v1 * f1b.x + v2 * f2b.x + v3 * f3b.x;
        acc.w += v0 * f0b.y + v1 * f1b.y + v2 * f2b.y + v3 * f3b.y;
    }
    for (; i < e; i++) {
        int   c = g_scol[i];
        float v = g_sval[i];
        __half2 pa = *(const __half2*)(hb + (size_t)c * FF);
        __half2 pb = *(const __half2*)(hb + (size_t)c * FF + 2);
        float2 fa = __half22float2(pa), fb = __half22float2(pb);
        acc.x += v * fa.x;
        acc.y += v * fa.y;
        acc.z += v * fb.x;
        acc.w += v * fb.y;
    }
    *(float4*)(out + ((size_t)b * NN + r) * FF + lane * 4) = acc;
}

// ---------------- launch --------------------------------------------------------
extern "C" void kernel_launch(void* const* d_in, const int* in_sizes, int n_in,
                              void* d_out, int out_size) {
    const float* x     = (const float*)d_in[0];
    const float* W     = (const float*)d_in[1];
    const void*  erow  = d_in[2];
    const void*  ecol  = d_in[3];
    const float* evals = (const float*)d_in[4];
    float*       out   = (float*)d_out;

    const int SMEM_B = 2 * 8192 * (int)sizeof(uint32_t);  // 64 KB
    cudaFuncSetAttribute(gemm_conv_kernel, cudaFuncAttributeMaxDynamicSharedMemorySize, SMEM_B);

    prep_kernel<<<16 + (NN + 255) / 256, 256>>>(W, (const unsigned int*)erow);
    gemm_conv_kernel<<<GEMM_BLOCKS + CONV_BLOCKS, 256, SMEM_B>>>(x, erow, ecol);
    scan_kernel<<<NBLK, 1024>>>();
    scatter_kernel<<<(EE / 2 + 255) / 256, 256>>>(evals);
    spmm_kernel<<<(BB * NN * 32 + 255) / 256, 256>>>(out);
}

// round 11
// speedup vs baseline: 1.3991x; 1.0036x over previous
#include <cuda_runtime.h>
#include <cuda_fp16.h>
#include <cstdint>

#define BB 4
#define NN 50000
#define EE 800000
#define FF 128
#define NBLK 49           // ceil(NN/1024)
#define NTILES 12500      // 16-row warp tiles (200000/16)
#define HB ((size_t)NN * FF)
#define GEMM_BLOCKS 296
#define CONV_BLOCKS ((EE / 2 + 255) / 256)   // 1563
#define SSBLK 148         // persistent scan+scatter blocks (1/SM)

// ---------------- scratch (__device__ globals: allocation-free) ----------------
__device__ __half   g_hh[(size_t)BB * NN * FF]; // projected features, fp16
__device__ int      g_cnt[NN];                  // per-row edge counts
__device__ int      g_off[NN + 1];              // CSR row offsets
__device__ int      g_pos[NN];                  // scatter cursors
__device__ int      g_erow[EE];                 // edge rows as int32
__device__ int      g_ecol[EE];                 // edge cols as int32
__device__ int2     g_edge[EE];                 // (col, val-bits) sorted by row
__device__ int      g_bsum[NBLK];               // scan block sums
__device__ int      g_sync1, g_sync2;           // grid barrier counters
__device__ int      g_idx64;                    // 1 if edge indices are int64

// ---------------- bf16 split helpers ------------------------------------------
__device__ __forceinline__ uint32_t pack_bf16_hi(float e0, float e1) {
    uint32_t r;
    asm("cvt.rn.bf16x2.f32 %0, %1, %2;" : "=r"(r) : "f"(e1), "f"(e0));
    return r;
}
__device__ __forceinline__ uint32_t pack_bf16_lo(uint32_t hi, float e0, float e1) {
    float h0 = __uint_as_float(hi << 16);
    float h1 = __uint_as_float(hi & 0xffff0000u);
    return pack_bf16_hi(e0 - h0, e1 - h1);
}

#define MMA16816(C, A0, A1, A2, A3, B0, B1)                                        \
    asm volatile("mma.sync.aligned.m16n8k16.row.col.f32.bf16.bf16.f32 "            \
                 "{%0,%1,%2,%3}, {%4,%5,%6,%7}, {%8,%9}, {%0,%1,%2,%3};"           \
                 : "+f"((C)[0]), "+f"((C)[1]), "+f"((C)[2]), "+f"((C)[3])          \
                 : "r"(A0), "r"(A1), "r"(A2), "r"(A3), "r"(B0), "r"(B1))

// ---------------- prep: zero counters + dtype detect + barrier reset -----------
__global__ void prep_kernel(const unsigned int* __restrict__ erow_words) {
    int i = blockIdx.x * blockDim.x + threadIdx.x;
    if (i < NN) g_cnt[i] = 0;
    if (i == 0) {
        // int64 indices < 2^32 have every odd 32-bit word == 0 (little-endian)
        int all0 = 1;
        for (int w = 1; w < 128; w += 2)
            if (erow_words[w] != 0u) all0 = 0;
        g_idx64 = all0;
        g_sync1 = 0;
        g_sync2 = 0;
    }
}

// ---------------- GEMM (blocks < GEMM_BLOCKS) + index convert (rest) -----------
// GEMM: h = x @ W^T via split-bf16 tensor MMA, fp16 result. B fragments built
// in-smem directly from W (L2-resident). Convert: widen indices + histogram.
__global__ void __launch_bounds__(256) gemm_conv_kernel(const float* __restrict__ x,
                                                        const float* __restrict__ W,
                                                        const void* __restrict__ erow,
                                                        const void* __restrict__ ecol) {
    if (blockIdx.x >= GEMM_BLOCKS) {
        int t = (blockIdx.x - GEMM_BLOCKS) * 256 + threadIdx.x;
        int e = t * 2;
        if (e >= EE) return;
        int r0, r1, c0, c1;
        if (g_idx64) {
            ulonglong2 R = ((const ulonglong2*)erow)[t];
            ulonglong2 C = ((const ulonglong2*)ecol)[t];
            r0 = (int)R.x; r1 = (int)R.y;
            c0 = (int)C.x; c1 = (int)C.y;
        } else {
            int2 R = ((const int2*)erow)[t];
            int2 C = ((const int2*)ecol)[t];
            r0 = R.x; r1 = R.y;
            c0 = C.x; c1 = C.y;
        }
        *(int2*)(g_erow + e) = make_int2(r0, r1);
        *(int2*)(g_ecol + e) = make_int2(c0, c1);
        atomicAdd(&g_cnt[r0], 1);
        atomicAdd(&g_cnt[r1], 1);
        return;
    }

    extern __shared__ uint32_t sB[];
    uint32_t* sBhi = sB;           // [8][16][32][2] = 8192
    uint32_t* sBlo = sB + 8192;

    // Build fragment tables from W: entry idx -> (rr, lane, nt, ks)
    #pragma unroll 4
    for (int j = 0; j < 32; j++) {
        int idx = threadIdx.x * 32 + j;
        int rr = idx & 1, ln = (idx >> 1) & 31, nt = (idx >> 6) & 15, ks = idx >> 10;
        int n = nt * 8 + (ln >> 2);
        int k0 = ks * 16 + (ln & 3) * 2 + rr * 8;
        float2 e = *(const float2*)(W + n * FF + k0);
        uint32_t hi = pack_bf16_hi(e.x, e.y);
        sBhi[idx] = hi;
        sBlo[idx] = pack_bf16_lo(hi, e.x, e.y);
    }
    __syncthreads();

    const int lane = threadIdx.x & 31;
    const int warp = threadIdx.x >> 5;
    const int grp = lane >> 2, tig = lane & 3;
    const int nwarps = GEMM_BLOCKS * 8;

    for (int tile = blockIdx.x * 8 + warp; tile < NTILES; tile += nwarps) {
        const int row0 = tile * 16;
        const float* xr0 = x + (size_t)(row0 + grp) * FF;       // rows grp, grp+8
        const float* xr1 = x + (size_t)(row0 + grp + 8) * FF;

        float acc[16][4];
        #pragma unroll
        for (int nt = 0; nt < 16; nt++)
            #pragma unroll
            for (int j = 0; j < 4; j++) acc[nt][j] = 0.0f;

        #pragma unroll 2
        for (int ks = 0; ks < 8; ks++) {
            const int c0 = ks * 16 + tig * 2;
            float2 f0 = *(const float2*)(xr0 + c0);
            float2 f1 = *(const float2*)(xr1 + c0);
            float2 f2 = *(const float2*)(xr0 + c0 + 8);
            float2 f3 = *(const float2*)(xr1 + c0 + 8);

            uint32_t ah0 = pack_bf16_hi(f0.x, f0.y), al0 = pack_bf16_lo(ah0, f0.x, f0.y);
            uint32_t ah1 = pack_bf16_hi(f1.x, f1.y), al1 = pack_bf16_lo(ah1, f1.x, f1.y);
            uint32_t ah2 = pack_bf16_hi(f2.x, f2.y), al2 = pack_bf16_lo(ah2, f2.x, f2.y);
            uint32_t ah3 = pack_bf16_hi(f3.x, f3.y), al3 = pack_bf16_lo(ah3, f3.x, f3.y);

            const uint32_t* bh = sBhi + (ks * 16 * 32 + lane) * 2;
            const uint32_t* bl = sBlo + (ks * 16 * 32 + lane) * 2;
            #pragma unroll
            for (int nt = 0; nt < 16; nt++) {
                uint32_t b0h = bh[nt * 64], b1h = bh[nt * 64 + 1];
                uint32_t b0l = bl[nt * 64], b1l = bl[nt * 64 + 1];
                MMA16816(acc[nt], ah0, ah1, ah2, ah3, b0h, b1h);  // hi*hi
                MMA16816(acc[nt], ah0, ah1, ah2, ah3, b0l, b1l);  // hi*lo
                MMA16816(acc[nt], al0, al1, al2, al3, b0h, b1h);  // lo*hi
            }
        }

        __half* h0 = g_hh + (size_t)(row0 + grp) * FF;
        __half* h1 = g_hh + (size_t)(row0 + grp + 8) * FF;
        #pragma unroll
        for (int nt = 0; nt < 16; nt++) {
            int col = nt * 8 + tig * 2;
            *(__half2*)(h0 + col) = __float22half2_rn(make_float2(acc[nt][0], acc[nt][1]));
            *(__half2*)(h1 + col) = __float22half2_rn(make_float2(acc[nt][2], acc[nt][3]));
        }
    }
}

// ---------------- fused scan + scatter: persistent 148 blocks ------------------
__device__ __forceinline__ void grid_barrier(int* ctr) {
    __syncthreads();
    if (threadIdx.x == 0) {
        __threadfence();
        atomicAdd(ctr, 1);
        while (atomicAdd(ctr, 0) < SSBLK) { }
    }
    __syncthreads();
}

__global__ void __launch_bounds__(1024) scan_scatter_kernel(const float* __restrict__ evals) {
    __shared__ int smv[1024];
    int incl = 0, cnt = 0;
    int i = blockIdx.x * 1024 + threadIdx.x;

    if (blockIdx.x < NBLK) {
        cnt = (i < NN) ? g_cnt[i] : 0;
        smv[threadIdx.x] = cnt;
        __syncthreads();
        for (int d = 1; d < 1024; d <<= 1) {
            int t = (threadIdx.x >= d) ? smv[threadIdx.x - d] : 0;
            __syncthreads();
            smv[threadIdx.x] += t;
            __syncthreads();
        }
        incl = smv[threadIdx.x];
        if (threadIdx.x == 1023) g_bsum[blockIdx.x] = incl;
    }

    grid_barrier(&g_sync1);

    if (blockIdx.x < NBLK) {
        __shared__ int sprefix;
        if (threadIdx.x == 0) {
            int run = 0;
            for (int b = 0; b < (int)blockIdx.x; b++) run += g_bsum[b];
            sprefix = run;
        }
        __syncthreads();
        if (i < NN) {
            int excl = incl - cnt + sprefix;
            g_off[i] = excl;
            g_pos[i] = excl;
        }
        if (i == 0) g_off[NN] = EE;
    }

    grid_barrier(&g_sync2);

    // scatter: grid-strided, 2 edges per task, packed (col,val) single store
    for (int t = blockIdx.x * 1024 + threadIdx.x; t < EE / 2; t += SSBLK * 1024) {
        int e = t * 2;
        int2   R = *(const int2*)(g_erow + e);
        int2   C = *(const int2*)(g_ecol + e);
        float2 V = *(const float2*)(evals + e);
        int p0 = atomicAdd(&g_pos[R.x], 1);
        g_edge[p0] = make_int2(C.x, __float_as_int(V.x));
        int p1 = atomicAdd(&g_pos[R.y], 1);
        g_edge[p1] = make_int2(C.y, __float_as_int(V.y));
    }
}

// ---------------- SpMM: one warp per (batch,row), batch-major, fp16 gathers ----
__global__ void __launch_bounds__(128) spmm_kernel(float* __restrict__ out) {
    int wg = (blockIdx.x * blockDim.x + threadIdx.x) >> 5;
    int lane = threadIdx.x & 31;
    if (wg >= BB * NN) return;
    int b = wg / NN;
    int r = wg - b * NN;

    int s = g_off[r];
    int e = g_off[r + 1];
    const __half* hb = g_hh + (size_t)b * HB + lane * 4;

    float4 acc = {0, 0, 0, 0};
    int i = s;
    for (; i + 3 < e; i += 4) {
        int2 e0 = g_edge[i],     e1 = g_edge[i + 1];
        int2 e2 = g_edge[i + 2], e3 = g_edge[i + 3];
        float v0 = __int_as_float(e0.y), v1 = __int_as_float(e1.y);
        float v2 = __int_as_float(e2.y), v3 = __int_as_float(e3.y);
        __half2 p0a = *(const __half2*)(hb + (size_t)e0.x * FF);
        __half2 p0b = *(const __half2*)(hb + (size_t)e0.x * FF + 2);
        __half2 p1a = *(const __half2*)(hb + (size_t)e1.x * FF);
        __half2 p1b = *(const __half2*)(hb + (size_t)e1.x * FF + 2);
        __half2 p2a = *(const __half2*)(hb + (size_t)e2.x * FF);
        __half2 p2b = *(const __half2*)(hb + (size_t)e2.x * FF + 2);
        __half2 p3a = *(const __half2*)(hb + (size_t)e3.x * FF);
        __half2 p3b = *(const __half2*)(hb + (size_t)e3.x * FF + 2);
        float2 f0a = __half22float2(p0a), f0b = __half22float2(p0b);
        float2 f1a = __half22float2(p1a), f1b = __half22float2(p1b);
        float2 f2a = __half22float2(p2a), f2b = __half22float2(p2b);
        float2 f3a = __half22float2(p3a), f3b = __half22float2(p3b);
        acc.x += v0 * f0a.x + v1 * f1a.x + v2 * f2a.x + v3 * f3a.x;
        acc.y += v0 * f0a.y + v1 * f1a.y + v2 * f2a.y + v3 * f3a.y;
        acc.z += v0 * f0b.x + v1 * f1b.x + v2 * f2b.x + v3 * f3b.x;
        acc.w += v0 * f0b.y + v1 * f1b.y + v2 * f2b.y + v3 * f3b.y;
    }
    for (; i < e; i++) {
        int2 ee = g_edge[i];
        float v = __int_as_float(ee.y);
        __half2 pa = *(const __half2*)(hb + (size_t)ee.x * FF);
        __half2 pb = *(const __half2*)(hb + (size_t)ee.x * FF + 2);
        float2 fa = __half22float2(pa), fb = __half22float2(pb);
        acc.x += v * fa.x;
        acc.y += v * fa.y;
        acc.z += v * fb.x;
        acc.w += v * fb.y;
    }
    *(float4*)(out + ((size_t)b * NN + r) * FF + lane * 4) = acc;
}

// ---------------- launch --------------------------------------------------------
extern "C" void kernel_launch(void* const* d_in, const int* in_sizes, int n_in,
                              void* d_out, int out_size) {
    const float* x     = (const float*)d_in[0];
    const float* W     = (const float*)d_in[1];
    const void*  erow  = d_in[2];
    const void*  ecol  = d_in[3];
    const float* evals = (const float*)d_in[4];
    float*       out   = (float*)d_out;

    const int SMEM_B = 2 * 8192 * (int)sizeof(uint32_t);  // 64 KB
    cudaFuncSetAttribute(gemm_conv_kernel, cudaFuncAttributeMaxDynamicSharedMemorySize, SMEM_B);

    prep_kernel<<<(NN + 255) / 256, 256>>>((const unsigned int*)erow);
    gemm_conv_kernel<<<GEMM_BLOCKS + CONV_BLOCKS, 256, SMEM_B>>>(x, W, erow, ecol);
    scan_scatter_kernel<<<SSBLK, 1024>>>(evals);
    spmm_kernel<<<(BB * NN * 32 + 127) / 128, 128>>>(out);
}

// round 16
// speedup vs baseline: 1.4839x; 1.0606x over previous
#include <cuda_runtime.h>
#include <cuda_fp16.h>
#include <cstdint>

#define BB 4
#define NN 50000
#define EE 800000
#define FF 128
#define NBLK 49           // ceil(NN/1024)
#define NTILES 12500      // 16-row warp tiles (200000/16)
#define HB ((size_t)NN * FF)
#define GEMM_BLOCKS 296
#define CONV_BLOCKS ((EE / 2 + 255) / 256)   // 1563
#define SSBLK 148         // persistent scan+scatter blocks (1/SM)

// ---------------- scratch (__device__ globals: allocation-free, zero-init) -----
__device__ __half       g_hh[(size_t)BB * NN * FF]; // projected features, fp16
__device__ int          g_cnt[NN];                  // per-row counts (re-zeroed each call)
__device__ int          g_off[NN + 1];              // CSR row offsets
__device__ int          g_pos[NN];                  // scatter cursors
__device__ int          g_erow[EE];                 // edge rows as int32
__device__ int          g_ecol[EE];                 // edge cols as int32
__device__ int2         g_edge[EE];                 // (col, val-bits) sorted by row
__device__ int          g_bsum[NBLK];               // scan block sums
__device__ unsigned int g_sync1, g_sync2;           // epoch grid-barrier counters

// ---------------- bf16 split helpers ------------------------------------------
__device__ __forceinline__ uint32_t pack_bf16_hi(float e0, float e1) {
    uint32_t r;
    asm("cvt.rn.bf16x2.f32 %0, %1, %2;" : "=r"(r) : "f"(e1), "f"(e0));
    return r;
}
__device__ __forceinline__ uint32_t pack_bf16_lo(uint32_t hi, float e0, float e1) {
    float h0 = __uint_as_float(hi << 16);
    float h1 = __uint_as_float(hi & 0xffff0000u);
    return pack_bf16_hi(e0 - h0, e1 - h1);
}

#define MMA16816(C, A0, A1, A2, A3, B0, B1)                                        \
    asm volatile("mma.sync.aligned.m16n8k16.row.col.f32.bf16.bf16.f32 "            \
                 "{%0,%1,%2,%3}, {%4,%5,%6,%7}, {%8,%9}, {%0,%1,%2,%3};"           \
                 : "+f"((C)[0]), "+f"((C)[1]), "+f"((C)[2]), "+f"((C)[3])          \
                 : "r"(A0), "r"(A1), "r"(A2), "r"(A3), "r"(B0), "r"(B1))

// ---------------- GEMM (blocks < GEMM_BLOCKS) + index convert (rest) -----------
// GEMM: h = x @ W^T via split-bf16 tensor MMA, fp16 result. B fragments built
// in-smem directly from W. Convert: widen indices + histogram (needs g_cnt
// zeroed: guaranteed by zero-init at load + re-zero in scan_scatter each call).
__global__ void __launch_bounds__(256) gemm_conv_kernel(const float* __restrict__ x,
                                                        const float* __restrict__ W,
                                                        const void* __restrict__ erow,
                                                        const void* __restrict__ ecol) {
    if (blockIdx.x >= GEMM_BLOCKS) {
        // dtype probe: int64 indices < 2^32 have every odd 32-bit word == 0
        __shared__ int sidx64;
        if (threadIdx.x == 0) {
            const unsigned int* w = (const unsigned int*)erow;
            int all0 = 1;
            for (int j = 1; j < 128; j += 2)
                if (w[j] != 0u) all0 = 0;
            sidx64 = all0;
        }
        __syncthreads();
        int t = (blockIdx.x - GEMM_BLOCKS) * 256 + threadIdx.x;
        int e = t * 2;
        if (e >= EE) return;
        int r0, r1, c0, c1;
        if (sidx64) {
            ulonglong2 R = ((const ulonglong2*)erow)[t];
            ulonglong2 C = ((const ulonglong2*)ecol)[t];
            r0 = (int)R.x; r1 = (int)R.y;
            c0 = (int)C.x; c1 = (int)C.y;
        } else {
            int2 R = ((const int2*)erow)[t];
            int2 C = ((const int2*)ecol)[t];
            r0 = R.x; r1 = R.y;
            c0 = C.x; c1 = C.y;
        }
        *(int2*)(g_erow + e) = make_int2(r0, r1);
        *(int2*)(g_ecol + e) = make_int2(c0, c1);
        atomicAdd(&g_cnt[r0], 1);
        atomicAdd(&g_cnt[r1], 1);
        return;
    }

    extern __shared__ uint32_t sB[];
    uint32_t* sBhi = sB;           // [8][16][32][2] = 8192
    uint32_t* sBlo = sB + 8192;

    // Build fragment tables from W: entry idx -> (rr, lane, nt, ks)
    #pragma unroll 4
    for (int j = 0; j < 32; j++) {
        int idx = threadIdx.x * 32 + j;
        int rr = idx & 1, ln = (idx >> 1) & 31, nt = (idx >> 6) & 15, ks = idx >> 10;
        int n = nt * 8 + (ln >> 2);
        int k0 = ks * 16 + (ln & 3) * 2 + rr * 8;
        float2 e = *(const float2*)(W + n * FF + k0);
        uint32_t hi = pack_bf16_hi(e.x, e.y);
        sBhi[idx] = hi;
        sBlo[idx] = pack_bf16_lo(hi, e.x, e.y);
    }
    __syncthreads();

    const int lane = threadIdx.x & 31;
    const int warp = threadIdx.x >> 5;
    const int grp = lane >> 2, tig = lane & 3;
    const int nwarps = GEMM_BLOCKS * 8;

    for (int tile = blockIdx.x * 8 + warp; tile < NTILES; tile += nwarps) {
        const int row0 = tile * 16;
        const float* xr0 = x + (size_t)(row0 + grp) * FF;       // rows grp, grp+8
        const float* xr1 = x + (size_t)(row0 + grp + 8) * FF;

        float acc[16][4];
        #pragma unroll
        for (int nt = 0; nt < 16; nt++)
            #pragma unroll
            for (int j = 0; j < 4; j++) acc[nt][j] = 0.0f;

        #pragma unroll 2
        for (int ks = 0; ks < 8; ks++) {
            const int c0 = ks * 16 + tig * 2;
            float2 f0 = *(const float2*)(xr0 + c0);
            float2 f1 = *(const float2*)(xr1 + c0);
            float2 f2 = *(const float2*)(xr0 + c0 + 8);
            float2 f3 = *(const float2*)(xr1 + c0 + 8);

            uint32_t ah0 = pack_bf16_hi(f0.x, f0.y), al0 = pack_bf16_lo(ah0, f0.x, f0.y);
            uint32_t ah1 = pack_bf16_hi(f1.x, f1.y), al1 = pack_bf16_lo(ah1, f1.x, f1.y);
            uint32_t ah2 = pack_bf16_hi(f2.x, f2.y), al2 = pack_bf16_lo(ah2, f2.x, f2.y);
            uint32_t ah3 = pack_bf16_hi(f3.x, f3.y), al3 = pack_bf16_lo(ah3, f3.x, f3.y);

            const uint32_t* bh = sBhi + (ks * 16 * 32 + lane) * 2;
            const uint32_t* bl = sBlo + (ks * 16 * 32 + lane) * 2;
            #pragma unroll
            for (int nt = 0; nt < 16; nt++) {
                uint32_t b0h = bh[nt * 64], b1h = bh[nt * 64 + 1];
                uint32_t b0l = bl[nt * 64], b1l = bl[nt * 64 + 1];
                MMA16816(acc[nt], ah0, ah1, ah2, ah3, b0h, b1h);  // hi*hi
                MMA16816(acc[nt], ah0, ah1, ah2, ah3, b0l, b1l);  // hi*lo
                MMA16816(acc[nt], al0, al1, al2, al3, b0h, b1h);  // lo*hi
            }
        }

        __half* h0 = g_hh + (size_t)(row0 + grp) * FF;
        __half* h1 = g_hh + (size_t)(row0 + grp + 8) * FF;
        #pragma unroll
        for (int nt = 0; nt < 16; nt++) {
            int col = nt * 8 + tig * 2;
            *(__half2*)(h0 + col) = __float22half2_rn(make_float2(acc[nt][0], acc[nt][1]));
            *(__half2*)(h1 + col) = __float22half2_rn(make_float2(acc[nt][2], acc[nt][3]));
        }
    }
}

// ---------------- fused scan + scatter: persistent 148 blocks ------------------
// Epoch barrier: monotonic counter, target = next multiple of SSBLK. Never
// reset, so replays stay deterministic with no prep pass.
__device__ __forceinline__ void grid_barrier(unsigned int* ctr) {
    __syncthreads();
    if (threadIdx.x == 0) {
        __threadfence();
        unsigned int old = atomicAdd(ctr, 1u);
        unsigned int target = (old / SSBLK + 1u) * SSBLK;
        while (atomicAdd(ctr, 0u) < target) { }
    }
    __syncthreads();
}

__global__ void __launch_bounds__(1024) scan_scatter_kernel(const float* __restrict__ evals) {
    __shared__ int smv[1024];
    int incl = 0, cnt = 0;
    int i = blockIdx.x * 1024 + threadIdx.x;

    if (blockIdx.x < NBLK) {
        cnt = (i < NN) ? g_cnt[i] : 0;
        smv[threadIdx.x] = cnt;
        __syncthreads();
        for (int d = 1; d < 1024; d <<= 1) {
            int t = (threadIdx.x >= d) ? smv[threadIdx.x - d] : 0;
            __syncthreads();
            smv[threadIdx.x] += t;
            __syncthreads();
        }
        incl = smv[threadIdx.x];
        if (threadIdx.x == 1023) g_bsum[blockIdx.x] = incl;
    }

    grid_barrier(&g_sync1);

    if (blockIdx.x < NBLK) {
        __shared__ int sprefix;
        if (threadIdx.x == 0) {
            int run = 0;
            for (int b = 0; b < (int)blockIdx.x; b++) run += g_bsum[b];
            sprefix = run;
        }
        __syncthreads();
        if (i < NN) {
            int excl = incl - cnt + sprefix;
            g_off[i] = excl;
            g_pos[i] = excl;
            g_cnt[i] = 0;          // restore invariant for the next call
        }
        if (i == 0) g_off[NN] = EE;
    }

    grid_barrier(&g_sync2);

    // scatter: grid-strided, 2 edges per task, packed (col,val) single store
    for (int t = blockIdx.x * 1024 + threadIdx.x; t < EE / 2; t += SSBLK * 1024) {
        int e = t * 2;
        int2   R = *(const int2*)(g_erow + e);
        int2   C = *(const int2*)(g_ecol + e);
        float2 V = *(const float2*)(evals + e);
        int p0 = atomicAdd(&g_pos[R.x], 1);
        g_edge[p0] = make_int2(C.x, __float_as_int(V.x));
        int p1 = atomicAdd(&g_pos[R.y], 1);
        g_edge[p1] = make_int2(C.y, __float_as_int(V.y));
    }
}

// ---------------- SpMM: one warp per (batch,row), batch-major, fp16 gathers ----
// One LDG.64 per lane per edge (8 contiguous bytes) — minimum L1 sector count.
__global__ void __launch_bounds__(128) spmm_kernel(float* __restrict__ out) {
    int wg = (blockIdx.x * blockDim.x + threadIdx.x) >> 5;
    int lane = threadIdx.x & 31;
    if (wg >= BB * NN) return;
    int b = wg / NN;
    int r = wg - b * NN;

    int s = g_off[r];
    int e = g_off[r + 1];
    const __half* hb = g_hh + (size_t)b * HB + lane * 4;

    float4 acc = {0, 0, 0, 0};
    int i = s;
    for (; i + 3 < e; i += 4) {
        int2 e0 = g_edge[i],     e1 = g_edge[i + 1];
        int2 e2 = g_edge[i + 2], e3 = g_edge[i + 3];
        float v0 = __int_as_float(e0.y), v1 = __int_as_float(e1.y);
        float v2 = __int_as_float(e2.y), v3 = __int_as_float(e3.y);
        uint2 q0 = *(const uint2*)(hb + (size_t)e0.x * FF);
        uint2 q1 = *(const uint2*)(hb + (size_t)e1.x * FF);
        uint2 q2 = *(const uint2*)(hb + (size_t)e2.x * FF);
        uint2 q3 = *(const uint2*)(hb + (size_t)e3.x * FF);
        float2 f0a = __half22float2(*(const __half2*)&q0.x);
        float2 f0b = __half22float2(*(const __half2*)&q0.y);
        float2 f1a = __half22float2(*(const __half2*)&q1.x);
        float2 f1b = __half22float2(*(const __half2*)&q1.y);
        float2 f2a = __half22float2(*(const __half2*)&q2.x);
        float2 f2b = __half22float2(*(const __half2*)&q2.y);
        float2 f3a = __half22float2(*(const __half2*)&q3.x);
        float2 f3b = __half22float2(*(const __half2*)&q3.y);
        acc.x += v0 * f0a.x + v1 * f1a.x + v2 * f2a.x + v3 * f3a.x;
        acc.y += v0 * f0a.y + v1 * f1a.y + v2 * f2a.y + v3 * f3a.y;
        acc.z += v0 * f0b.x + v1 * f1b.x + v2 * f2b.x + v3 * f3b.x;
        acc.w += v0 * f0b.y + v1 * f1b.y + v2 * f2b.y + v3 * f3b.y;
    }
    for (; i < e; i++) {
        int2 ee = g_edge[i];
        float v = __int_as_float(ee.y);
        uint2 q = *(const uint2*)(hb + (size_t)ee.x * FF);
        float2 fa = __half22float2(*(const __half2*)&q.x);
        float2 fb = __half22float2(*(const __half2*)&q.y);
        acc.x += v * fa.x;
        acc.y += v * fa.y;
        acc.z += v * fb.x;
        acc.w += v * fb.y;
    }
    *(float4*)(out + ((size_t)b * NN + r) * FF + lane * 4) = acc;
}

// ---------------- launch --------------------------------------------------------
extern "C" void kernel_launch(void* const* d_in, const int* in_sizes, int n_in,
                              void* d_out, int out_size) {
    const float* x     = (const float*)d_in[0];
    const float* W     = (const float*)d_in[1];
    const void*  erow  = d_in[2];
    const void*  ecol  = d_in[3];
    const float* evals = (const float*)d_in[4];
    float*       out   = (float*)d_out;

    const int SMEM_B = 2 * 8192 * (int)sizeof(uint32_t);  // 64 KB
    cudaFuncSetAttribute(gemm_conv_kernel, cudaFuncAttributeMaxDynamicSharedMemorySize, SMEM_B);

    gemm_conv_kernel<<<GEMM_BLOCKS + CONV_BLOCKS, 256, SMEM_B>>>(x, W, erow, ecol);
    scan_scatter_kernel<<<SSBLK, 1024>>>(evals);
    spmm_kernel<<<(BB * NN * 32 + 127) / 128, 128>>>(out);
}